// round 13
// baseline (speedup 1.0000x reference)
#include <cuda_runtime.h>
#include <cuda_fp16.h>
#include <math.h>
#include <stdint.h>

#define Bq 4
#define Sq 4096
#define Dq 1024
#define Nq 16
#define Mq (Bq*Sq)      /* 16384 rows */
#define Kq Dq           /* 1024 */
#define NCAT 2080
#define NPAD 2176       /* 17*128 */

/* ---- scratch ---- */
__device__ float g_h[Mq * Dq];          /* LN out, row-major (GEMM A + epilogue reload) */
__device__ float g_deltaT[Bq * Dq * Sq]; /* softplus, transposed [b][d][s] */
__device__ float g_dthT[Bq * Dq * Sq];   /* softplus * h, transposed */
__device__ float g_linT[Bq * Dq * Sq];   /* h@WD + bD + x, transposed */
__device__ float g_BcT[Bq * Nq * Sq];    /* [b][n][s] */
__device__ float g_CcT[Bq * Nq * Sq];
__device__ float g_bcat[NPAD];
__device__ float g_A2[Dq * Nq];
__device__ __half g_hh[Mq * Kq];
__device__ __half g_Wh[NPAD * Kq];

__device__ __forceinline__ uint32_t smem_u32(const void* p) {
    uint32_t r;
    asm("{ .reg .u64 t; cvta.to.shared.u64 t, %1; cvt.u32.u64 %0, t; }" : "=r"(r) : "l"(p));
    return r;
}

/* ---------------- prep ---------------- */
__global__ void prep_kernel(const float* __restrict__ logA,
                            const float* __restrict__ Wd, const float* __restrict__ bd,
                            const float* __restrict__ Wb, const float* __restrict__ bb,
                            const float* __restrict__ Wc, const float* __restrict__ bc,
                            const float* __restrict__ WD, const float* __restrict__ bD)
{
    int r = blockIdx.x;
    int tid = threadIdx.x;       /* 256 */
    const float* src = 0;
    if (r < 1024)        src = Wd + (size_t)r * Kq;
    else if (r < 2048)   src = WD + (size_t)(r - 1024) * Kq;
    else if (r < 2064)   src = Wb + (size_t)(r - 2048) * Kq;
    else if (r < NCAT)   src = Wc + (size_t)(r - 2064) * Kq;

    float4 v = src ? reinterpret_cast<const float4*>(src)[tid]
                   : make_float4(0.f, 0.f, 0.f, 0.f);
    __half q[4];
    q[0] = __float2half_rn(v.x); q[1] = __float2half_rn(v.y);
    q[2] = __float2half_rn(v.z); q[3] = __float2half_rn(v.w);
    *reinterpret_cast<uint2*>(g_Wh + (size_t)r * Kq + tid * 4) = *reinterpret_cast<uint2*>(q);

    if (tid == 0) {
        float bv = 0.f;
        if (r < 1024)      bv = bd[r];
        else if (r < 2048) bv = bD[r - 1024];
        else if (r < 2064) bv = bb[r - 2048];
        else if (r < NCAT) bv = bc[r - 2064];
        g_bcat[r] = bv;
    }
    if (r < Dq && tid < Nq) {
        g_A2[r * Nq + tid] = -expf(logA[r * Nq + tid]) * 1.44269504088896340736f;
    }
}

/* ---------------- layernorm: fp32 out + fp16 out ---------------- */
__global__ void ln_kernel(const float* __restrict__ x,
                          const float* __restrict__ w,
                          const float* __restrict__ b)
{
    int row = blockIdx.x;
    int tid = threadIdx.x;       /* 256 */
    const float4* x4 = reinterpret_cast<const float4*>(x) + (size_t)row * 256;
    float4 v = x4[tid];
    float sum = v.x + v.y + v.z + v.w;
    float sq  = v.x*v.x + v.y*v.y + v.z*v.z + v.w*v.w;

    #pragma unroll
    for (int o = 16; o > 0; o >>= 1) {
        sum += __shfl_down_sync(0xffffffffu, sum, o);
        sq  += __shfl_down_sync(0xffffffffu, sq, o);
    }
    __shared__ float red0[8], red1[8];
    int warp = tid >> 5, lane = tid & 31;
    if (lane == 0) { red0[warp] = sum; red1[warp] = sq; }
    __syncthreads();
    if (tid < 32) {
        float s1 = (tid < 8) ? red0[tid] : 0.f;
        float s2 = (tid < 8) ? red1[tid] : 0.f;
        #pragma unroll
        for (int o = 4; o > 0; o >>= 1) {
            s1 += __shfl_down_sync(0xffffffffu, s1, o);
            s2 += __shfl_down_sync(0xffffffffu, s2, o);
        }
        if (tid == 0) { red0[0] = s1; red1[0] = s2; }
    }
    __syncthreads();
    float mean = red0[0] * (1.0f / Dq);
    float var  = red1[0] * (1.0f / Dq) - mean * mean;
    float rs   = rsqrtf(var + 1e-5f);

    float4 wv = reinterpret_cast<const float4*>(w)[tid];
    float4 bv = reinterpret_cast<const float4*>(b)[tid];
    float4 o;
    o.x = (v.x - mean) * rs * wv.x + bv.x;
    o.y = (v.y - mean) * rs * wv.y + bv.y;
    o.z = (v.z - mean) * rs * wv.z + bv.z;
    o.w = (v.w - mean) * rs * wv.w + bv.w;
    reinterpret_cast<float4*>(g_h)[(size_t)row * 256 + tid] = o;

    __half q[4];
    q[0] = __float2half_rn(o.x); q[1] = __float2half_rn(o.y);
    q[2] = __float2half_rn(o.z); q[3] = __float2half_rn(o.w);
    *reinterpret_cast<uint2*>(g_hh + (size_t)row * Kq + tid * 4) = *reinterpret_cast<uint2*>(q);
}

/* ====== HMMA GEMM: fp16 1-term, BK=32, 3-stage, 2 CTAs/SM ====== */
#define BK5 32
#define KPADB 80
#define PLANEB (128 * KPADB)
#define STAGEB (2 * PLANEB)
#define NSTG 3
#define GSMEM (NSTG * STAGEB)     /* 61440 B */
#define NCHK5 (Kq / BK5)          /* 32 */

__device__ __forceinline__ void cp16(uint32_t dst, const void* src) {
    asm volatile("cp.async.cg.shared.global [%0], [%1], 16;" :: "r"(dst), "l"(src) : "memory");
}
__device__ __forceinline__ void cp_commit() {
    asm volatile("cp.async.commit_group;" ::: "memory");
}
template<int N> __device__ __forceinline__ void cp_wait() {
    asm volatile("cp.async.wait_group %0;" :: "n"(N) : "memory");
}
__device__ __forceinline__ void ldm_x4(uint32_t addr, uint32_t* r) {
    asm volatile("ldmatrix.sync.aligned.m8n8.x4.shared.b16 {%0,%1,%2,%3}, [%4];"
                 : "=r"(r[0]), "=r"(r[1]), "=r"(r[2]), "=r"(r[3]) : "r"(addr));
}
__device__ __forceinline__ void mma_f16(float* c, const uint32_t* a, const uint32_t* b) {
    asm volatile("mma.sync.aligned.m16n8k16.row.col.f32.f16.f16.f32 "
                 "{%0,%1,%2,%3}, {%4,%5,%6,%7}, {%8,%9}, {%0,%1,%2,%3};"
                 : "+f"(c[0]), "+f"(c[1]), "+f"(c[2]), "+f"(c[3])
                 : "r"(a[0]), "r"(a[1]), "r"(a[2]), "r"(a[3]), "r"(b[0]), "r"(b[1]));
}
__device__ __forceinline__ float softplus_f(float v) {
    return fmaxf(v, 0.f) + log1pf(expf(-fabsf(v)));
}

__device__ __forceinline__ void fill_stage(uint32_t sbase, int kc, int tid,
                                           const __half* A, const __half* B)
{
    const __half* srcs[2] = {A, B};
    #pragma unroll
    for (int p = 0; p < 2; p++) {
        #pragma unroll
        for (int i = 0; i < 2; i++) {
            int id = tid + i * 256;
            int row = id >> 2, q = id & 3;
            cp16(sbase + p * PLANEB + row * KPADB + q * 16,
                 srcs[p] + (size_t)row * Kq + kc * BK5 + q * 8);
        }
    }
}

__global__ __launch_bounds__(256, 2)
void gemm_hmma_kernel(const float* __restrict__ xres)
{
    extern __shared__ __align__(16) char dynsm[];
    uint32_t smb = smem_u32(dynsm);

    int tid  = threadIdx.x;
    int wid  = tid >> 5, lane = tid & 31;
    int n0   = blockIdx.x * 128;
    int m0   = blockIdx.y * 128;
    int wm   = wid >> 1;
    int wn   = wid & 1;

    const __half* Ah = g_hh + (size_t)m0 * Kq;
    const __half* Bh = g_Wh + (size_t)n0 * Kq;

    float acc[2][8][4];
    #pragma unroll
    for (int i = 0; i < 2; i++)
        #pragma unroll
        for (int j = 0; j < 8; j++)
            #pragma unroll
            for (int k = 0; k < 4; k++) acc[i][j][k] = 0.f;

    uint32_t a_off[2], b_off[8];
    #pragma unroll
    for (int mt = 0; mt < 2; mt++)
        a_off[mt] = (uint32_t)((wm * 32 + (lane & 15) + mt * 16) * KPADB + (lane >> 4) * 16);
    #pragma unroll
    for (int p = 0; p < 4; p++)
        b_off[p] = (uint32_t)((wn * 64 + (lane & 7) + ((lane >> 4) * 8) + p * 16) * KPADB
                              + ((lane >> 3) & 1) * 16);

    fill_stage(smb + 0 * STAGEB, 0, tid, Ah, Bh); cp_commit();
    fill_stage(smb + 1 * STAGEB, 1, tid, Ah, Bh); cp_commit();

    for (int kc = 0; kc < NCHK5; kc++) {
        int buf = kc % NSTG;
        if (kc == NCHK5 - 1) cp_wait<0>(); else cp_wait<1>();
        __syncthreads();
        if (kc + 2 < NCHK5) {
            fill_stage(smb + ((kc + 2) % NSTG) * STAGEB, kc + 2, tid, Ah, Bh);
            cp_commit();
        }

        uint32_t base = smb + buf * STAGEB;
        #pragma unroll
        for (int kk = 0; kk < 2; kk++) {
            uint32_t ko = (uint32_t)(kk * 32);
            uint32_t a[2][4], bt[8][2];
            #pragma unroll
            for (int mt = 0; mt < 2; mt++)
                ldm_x4(base + 0 * PLANEB + a_off[mt] + ko, a[mt]);
            #pragma unroll
            for (int p = 0; p < 4; p++) {
                uint32_t r4[4];
                ldm_x4(base + 1 * PLANEB + b_off[p] + ko, r4);
                bt[2*p][0] = r4[0]; bt[2*p][1] = r4[1];
                bt[2*p+1][0] = r4[2]; bt[2*p+1][1] = r4[3];
            }
            #pragma unroll
            for (int mt = 0; mt < 2; mt++)
                #pragma unroll
                for (int nt = 0; nt < 8; nt++)
                    mma_f16(acc[mt][nt], a[mt], bt[nt]);
        }
    }

    /* epilogue: bias + routing; transposed stores; dth fused */
    int qrow = lane >> 2;
    int qcol = (lane & 3) * 2;
    #pragma unroll
    for (int mt = 0; mt < 2; mt++) {
        #pragma unroll
        for (int half = 0; half < 2; half++) {
            int m  = m0 + wm * 32 + mt * 16 + qrow + half * 8;
            int bb = m >> 12;
            int ss = m & (Sq - 1);
            #pragma unroll
            for (int nt = 0; nt < 8; nt++) {
                int col = n0 + wn * 64 + nt * 8 + qcol;
                if (col >= NCAT) continue;
                float v0 = acc[mt][nt][half * 2 + 0] + g_bcat[col];
                float v1 = acc[mt][nt][half * 2 + 1] + g_bcat[col + 1];
                if (col < 1024) {
                    float2 hv = *reinterpret_cast<const float2*>(g_h + (size_t)m * Dq + col);
                    float sp0 = softplus_f(v0), sp1 = softplus_f(v1);
                    size_t base = ((size_t)bb * Dq + col) * Sq + ss;
                    g_deltaT[base]      = sp0;
                    g_deltaT[base + Sq] = sp1;
                    g_dthT[base]        = sp0 * hv.x;
                    g_dthT[base + Sq]   = sp1 * hv.y;
                } else if (col < 2048) {
                    int cc = col - 1024;
                    float2 xr = *reinterpret_cast<const float2*>(xres + (size_t)m * Dq + cc);
                    size_t base = ((size_t)bb * Dq + cc) * Sq + ss;
                    g_linT[base]      = v0 + xr.x;
                    g_linT[base + Sq] = v1 + xr.y;
                } else if (col < 2064) {
                    int cc = col - 2048;
                    size_t base = ((size_t)bb * Nq + cc) * Sq + ss;
                    g_BcT[base]      = v0;
                    g_BcT[base + Sq] = v1;
                } else {
                    int cc = col - 2064;
                    size_t base = ((size_t)bb * Nq + cc) * Sq + ss;
                    g_CcT[base]      = v0;
                    g_CcT[base + Sq] = v1;
                }
            }
        }
    }
}

/* ====== scan v5: transposed streams, float4 loads along t ====== */
#define TP 8
__device__ __forceinline__ float ex2f(float x) {
    float r;
    asm("ex2.approx.f32 %0, %1;" : "=f"(r) : "f"(x));
    return r;
}

__global__ __launch_bounds__(64)
void scan_kernel(float* __restrict__ out)
{
    int b    = blockIdx.y;
    int dblk = blockIdx.x;          /* 0..255 */
    int tid  = threadIdx.x;         /* 64 = 4 d x 16 n */
    int n    = tid & 15;
    int td   = tid >> 4;
    int d    = dblk * 4 + td;

    float a2 = g_A2[d * Nq + n];
    float s  = 0.f;

    const float* dtp = g_deltaT + ((size_t)b * Dq + d) * Sq;
    const float* dhp = g_dthT   + ((size_t)b * Dq + d) * Sq;
    const float* llp = g_linT   + ((size_t)b * Dq + d) * Sq;
    const float* bnp = g_BcT    + ((size_t)b * Nq + n) * Sq;
    const float* cnp = g_CcT    + ((size_t)b * Nq + n) * Sq;
    float* outp = out + (size_t)b * Sq * Dq + d;

    float dt0[TP], dh0[TP], ll0[TP], bn0[TP], cn0[TP];
    float dt1[TP], dh1[TP], ll1[TP], bn1[TP], cn1[TP];

    *reinterpret_cast<float4*>(&dt0[0]) = *reinterpret_cast<const float4*>(dtp + 0);
    *reinterpret_cast<float4*>(&dt0[4]) = *reinterpret_cast<const float4*>(dtp + 4);
    *reinterpret_cast<float4*>(&dh0[0]) = *reinterpret_cast<const float4*>(dhp + 0);
    *reinterpret_cast<float4*>(&dh0[4]) = *reinterpret_cast<const float4*>(dhp + 4);
    *reinterpret_cast<float4*>(&ll0[0]) = *reinterpret_cast<const float4*>(llp + 0);
    *reinterpret_cast<float4*>(&ll0[4]) = *reinterpret_cast<const float4*>(llp + 4);
    *reinterpret_cast<float4*>(&bn0[0]) = *reinterpret_cast<const float4*>(bnp + 0);
    *reinterpret_cast<float4*>(&bn0[4]) = *reinterpret_cast<const float4*>(bnp + 4);
    *reinterpret_cast<float4*>(&cn0[0]) = *reinterpret_cast<const float4*>(cnp + 0);
    *reinterpret_cast<float4*>(&cn0[4]) = *reinterpret_cast<const float4*>(cnp + 4);

    const int NT = Sq / TP;          /* 512 */
    for (int j = 0; j < NT; j++) {
        int t0 = j * TP;
        if (j + 1 < NT) {
            int t1 = t0 + TP;
            *reinterpret_cast<float4*>(&dt1[0]) = *reinterpret_cast<const float4*>(dtp + t1);
            *reinterpret_cast<float4*>(&dt1[4]) = *reinterpret_cast<const float4*>(dtp + t1 + 4);
            *reinterpret_cast<float4*>(&dh1[0]) = *reinterpret_cast<const float4*>(dhp + t1);
            *reinterpret_cast<float4*>(&dh1[4]) = *reinterpret_cast<const float4*>(dhp + t1 + 4);
            *reinterpret_cast<float4*>(&ll1[0]) = *reinterpret_cast<const float4*>(llp + t1);
            *reinterpret_cast<float4*>(&ll1[4]) = *reinterpret_cast<const float4*>(llp + t1 + 4);
            *reinterpret_cast<float4*>(&bn1[0]) = *reinterpret_cast<const float4*>(bnp + t1);
            *reinterpret_cast<float4*>(&bn1[4]) = *reinterpret_cast<const float4*>(bnp + t1 + 4);
            *reinterpret_cast<float4*>(&cn1[0]) = *reinterpret_cast<const float4*>(cnp + t1);
            *reinterpret_cast<float4*>(&cn1[4]) = *reinterpret_cast<const float4*>(cnp + t1 + 4);
        }

        /* phase 1: recurrence — critical path is TP chained FMAs */
        float pv[TP];
        #pragma unroll
        for (int k = 0; k < TP; k++) {
            float dA = ex2f(dt0[k] * a2);
            s = fmaf(dA, s, dh0[k] * bn0[k]);
            pv[k] = s * cn0[k];
        }

        /* phase 2: TP independent butterfly reductions, rounds interleaved */
        #pragma unroll
        for (int o = 1; o <= 8; o <<= 1) {
            float sh[TP];
            #pragma unroll
            for (int k = 0; k < TP; k++)
                sh[k] = __shfl_xor_sync(0xffffffffu, pv[k], o);
            #pragma unroll
            for (int k = 0; k < TP; k++)
                pv[k] += sh[k];
        }

        if (n == 0) {
            #pragma unroll
            for (int k = 0; k < TP; k++)
                outp[(size_t)(t0 + k) * Dq] = ll0[k] + pv[k];
        }

        #pragma unroll
        for (int k = 0; k < TP; k++) {
            dt0[k] = dt1[k]; dh0[k] = dh1[k]; ll0[k] = ll1[k];
            bn0[k] = bn1[k]; cn0[k] = cn1[k];
        }
    }
}

/* ------------------------------- launch ------------------------------- */
extern "C" void kernel_launch(void* const* d_in, const int* in_sizes, int n_in,
                              void* d_out, int out_size)
{
    const float* x    = (const float*)d_in[0];
    const float* logA = (const float*)d_in[1];
    const float* Wd   = (const float*)d_in[2];
    const float* bd   = (const float*)d_in[3];
    const float* Wb   = (const float*)d_in[4];
    const float* bb   = (const float*)d_in[5];
    const float* Wc   = (const float*)d_in[6];
    const float* bc   = (const float*)d_in[7];
    const float* WDp  = (const float*)d_in[8];
    const float* bD   = (const float*)d_in[9];
    const float* lnw  = (const float*)d_in[10];
    const float* lnb  = (const float*)d_in[11];
    float* out = (float*)d_out;

    cudaFuncSetAttribute(gemm_hmma_kernel,
                         cudaFuncAttributeMaxDynamicSharedMemorySize, GSMEM);

    prep_kernel<<<NPAD, 256>>>(logA, Wd, bd, Wb, bb, Wc, bc, WDp, bD);
    ln_kernel<<<Mq, 256>>>(x, lnw, lnb);
    dim3 ggrid(NPAD / 128, Mq / 128);            /* 17 x 128 */
    gemm_hmma_kernel<<<ggrid, 256, GSMEM>>>(x);
    dim3 sgrid(Dq / 4, Bq);                      /* 256 x 4 */
    scan_kernel<<<sgrid, 64>>>(out);
}

// round 14
// speedup vs baseline: 1.4720x; 1.4720x over previous
#include <cuda_runtime.h>
#include <cuda_fp16.h>
#include <math.h>
#include <stdint.h>

#define Bq 4
#define Sq 4096
#define Dq 1024
#define Nq 16
#define Mq (Bq*Sq)      /* 16384 rows */
#define Kq Dq           /* 1024 */
#define NCAT 2080
#define NPAD 2176       /* 17*128 */

/* ---- scratch (row-major: coalesced across lanes) ---- */
__device__ float g_h[Mq * Dq];
__device__ float g_delta[Mq * Dq];   /* softplus */
__device__ float g_dth[Mq * Dq];     /* softplus * h */
__device__ float g_lin[Mq * Dq];     /* h@WD + bD + x */
__device__ float g_Bc[Mq * Nq];
__device__ float g_Cc[Mq * Nq];
__device__ float g_bcat[NPAD];
__device__ float g_A2[Dq * Nq];
__device__ __half g_hh[Mq * Kq];
__device__ __half g_Wh[NPAD * Kq];

__device__ __forceinline__ uint32_t smem_u32(const void* p) {
    uint32_t r;
    asm("{ .reg .u64 t; cvta.to.shared.u64 t, %1; cvt.u32.u64 %0, t; }" : "=r"(r) : "l"(p));
    return r;
}

/* ---------------- prep ---------------- */
__global__ void prep_kernel(const float* __restrict__ logA,
                            const float* __restrict__ Wd, const float* __restrict__ bd,
                            const float* __restrict__ Wb, const float* __restrict__ bb,
                            const float* __restrict__ Wc, const float* __restrict__ bc,
                            const float* __restrict__ WD, const float* __restrict__ bD)
{
    int r = blockIdx.x;
    int tid = threadIdx.x;       /* 256 */
    const float* src = 0;
    if (r < 1024)        src = Wd + (size_t)r * Kq;
    else if (r < 2048)   src = WD + (size_t)(r - 1024) * Kq;
    else if (r < 2064)   src = Wb + (size_t)(r - 2048) * Kq;
    else if (r < NCAT)   src = Wc + (size_t)(r - 2064) * Kq;

    float4 v = src ? reinterpret_cast<const float4*>(src)[tid]
                   : make_float4(0.f, 0.f, 0.f, 0.f);
    __half q[4];
    q[0] = __float2half_rn(v.x); q[1] = __float2half_rn(v.y);
    q[2] = __float2half_rn(v.z); q[3] = __float2half_rn(v.w);
    *reinterpret_cast<uint2*>(g_Wh + (size_t)r * Kq + tid * 4) = *reinterpret_cast<uint2*>(q);

    if (tid == 0) {
        float bv = 0.f;
        if (r < 1024)      bv = bd[r];
        else if (r < 2048) bv = bD[r - 1024];
        else if (r < 2064) bv = bb[r - 2048];
        else if (r < NCAT) bv = bc[r - 2064];
        g_bcat[r] = bv;
    }
    if (r < Dq && tid < Nq) {
        g_A2[r * Nq + tid] = -expf(logA[r * Nq + tid]) * 1.44269504088896340736f;
    }
}

/* ---------------- layernorm: fp32 out + fp16 out ---------------- */
__global__ void ln_kernel(const float* __restrict__ x,
                          const float* __restrict__ w,
                          const float* __restrict__ b)
{
    int row = blockIdx.x;
    int tid = threadIdx.x;       /* 256 */
    const float4* x4 = reinterpret_cast<const float4*>(x) + (size_t)row * 256;
    float4 v = x4[tid];
    float sum = v.x + v.y + v.z + v.w;
    float sq  = v.x*v.x + v.y*v.y + v.z*v.z + v.w*v.w;

    #pragma unroll
    for (int o = 16; o > 0; o >>= 1) {
        sum += __shfl_down_sync(0xffffffffu, sum, o);
        sq  += __shfl_down_sync(0xffffffffu, sq, o);
    }
    __shared__ float red0[8], red1[8];
    int warp = tid >> 5, lane = tid & 31;
    if (lane == 0) { red0[warp] = sum; red1[warp] = sq; }
    __syncthreads();
    if (tid < 32) {
        float s1 = (tid < 8) ? red0[tid] : 0.f;
        float s2 = (tid < 8) ? red1[tid] : 0.f;
        #pragma unroll
        for (int o = 4; o > 0; o >>= 1) {
            s1 += __shfl_down_sync(0xffffffffu, s1, o);
            s2 += __shfl_down_sync(0xffffffffu, s2, o);
        }
        if (tid == 0) { red0[0] = s1; red1[0] = s2; }
    }
    __syncthreads();
    float mean = red0[0] * (1.0f / Dq);
    float var  = red1[0] * (1.0f / Dq) - mean * mean;
    float rs   = rsqrtf(var + 1e-5f);

    float4 wv = reinterpret_cast<const float4*>(w)[tid];
    float4 bv = reinterpret_cast<const float4*>(b)[tid];
    float4 o;
    o.x = (v.x - mean) * rs * wv.x + bv.x;
    o.y = (v.y - mean) * rs * wv.y + bv.y;
    o.z = (v.z - mean) * rs * wv.z + bv.z;
    o.w = (v.w - mean) * rs * wv.w + bv.w;
    reinterpret_cast<float4*>(g_h)[(size_t)row * 256 + tid] = o;

    __half q[4];
    q[0] = __float2half_rn(o.x); q[1] = __float2half_rn(o.y);
    q[2] = __float2half_rn(o.z); q[3] = __float2half_rn(o.w);
    *reinterpret_cast<uint2*>(g_hh + (size_t)row * Kq + tid * 4) = *reinterpret_cast<uint2*>(q);
}

/* ====== HMMA GEMM: fp16 1-term, BK=32, 3-stage, 2 CTAs/SM ====== */
#define BK5 32
#define KPADB 80
#define PLANEB (128 * KPADB)
#define STAGEB (2 * PLANEB)
#define NSTG 3
#define GSMEM (NSTG * STAGEB)     /* 61440 B */
#define NCHK5 (Kq / BK5)          /* 32 */

__device__ __forceinline__ void cp16(uint32_t dst, const void* src) {
    asm volatile("cp.async.cg.shared.global [%0], [%1], 16;" :: "r"(dst), "l"(src) : "memory");
}
__device__ __forceinline__ void cp4(uint32_t dst, const void* src) {
    asm volatile("cp.async.ca.shared.global [%0], [%1], 4;" :: "r"(dst), "l"(src) : "memory");
}
__device__ __forceinline__ void cp_commit() {
    asm volatile("cp.async.commit_group;" ::: "memory");
}
template<int N> __device__ __forceinline__ void cp_wait() {
    asm volatile("cp.async.wait_group %0;" :: "n"(N) : "memory");
}
__device__ __forceinline__ void ldm_x4(uint32_t addr, uint32_t* r) {
    asm volatile("ldmatrix.sync.aligned.m8n8.x4.shared.b16 {%0,%1,%2,%3}, [%4];"
                 : "=r"(r[0]), "=r"(r[1]), "=r"(r[2]), "=r"(r[3]) : "r"(addr));
}
__device__ __forceinline__ void mma_f16(float* c, const uint32_t* a, const uint32_t* b) {
    asm volatile("mma.sync.aligned.m16n8k16.row.col.f32.f16.f16.f32 "
                 "{%0,%1,%2,%3}, {%4,%5,%6,%7}, {%8,%9}, {%0,%1,%2,%3};"
                 : "+f"(c[0]), "+f"(c[1]), "+f"(c[2]), "+f"(c[3])
                 : "r"(a[0]), "r"(a[1]), "r"(a[2]), "r"(a[3]), "r"(b[0]), "r"(b[1]));
}
__device__ __forceinline__ float softplus_f(float v) {
    return fmaxf(v, 0.f) + log1pf(expf(-fabsf(v)));
}

__device__ __forceinline__ void fill_stage(uint32_t sbase, int kc, int tid,
                                           const __half* A, const __half* B)
{
    const __half* srcs[2] = {A, B};
    #pragma unroll
    for (int p = 0; p < 2; p++) {
        #pragma unroll
        for (int i = 0; i < 2; i++) {
            int id = tid + i * 256;
            int row = id >> 2, q = id & 3;
            cp16(sbase + p * PLANEB + row * KPADB + q * 16,
                 srcs[p] + (size_t)row * Kq + kc * BK5 + q * 8);
        }
    }
}

__global__ __launch_bounds__(256, 2)
void gemm_hmma_kernel(const float* __restrict__ xres)
{
    extern __shared__ __align__(16) char dynsm[];
    uint32_t smb = smem_u32(dynsm);

    int tid  = threadIdx.x;
    int wid  = tid >> 5, lane = tid & 31;
    int n0   = blockIdx.x * 128;
    int m0   = blockIdx.y * 128;
    int wm   = wid >> 1;
    int wn   = wid & 1;

    const __half* Ah = g_hh + (size_t)m0 * Kq;
    const __half* Bh = g_Wh + (size_t)n0 * Kq;

    float acc[2][8][4];
    #pragma unroll
    for (int i = 0; i < 2; i++)
        #pragma unroll
        for (int j = 0; j < 8; j++)
            #pragma unroll
            for (int k = 0; k < 4; k++) acc[i][j][k] = 0.f;

    uint32_t a_off[2], b_off[8];
    #pragma unroll
    for (int mt = 0; mt < 2; mt++)
        a_off[mt] = (uint32_t)((wm * 32 + (lane & 15) + mt * 16) * KPADB + (lane >> 4) * 16);
    #pragma unroll
    for (int p = 0; p < 4; p++)
        b_off[p] = (uint32_t)((wn * 64 + (lane & 7) + ((lane >> 4) * 8) + p * 16) * KPADB
                              + ((lane >> 3) & 1) * 16);

    fill_stage(smb + 0 * STAGEB, 0, tid, Ah, Bh); cp_commit();
    fill_stage(smb + 1 * STAGEB, 1, tid, Ah, Bh); cp_commit();

    for (int kc = 0; kc < NCHK5; kc++) {
        int buf = kc % NSTG;
        if (kc == NCHK5 - 1) cp_wait<0>(); else cp_wait<1>();
        __syncthreads();
        if (kc + 2 < NCHK5) {
            fill_stage(smb + ((kc + 2) % NSTG) * STAGEB, kc + 2, tid, Ah, Bh);
            cp_commit();
        }

        uint32_t base = smb + buf * STAGEB;
        #pragma unroll
        for (int kk = 0; kk < 2; kk++) {
            uint32_t ko = (uint32_t)(kk * 32);
            uint32_t a[2][4], bt[8][2];
            #pragma unroll
            for (int mt = 0; mt < 2; mt++)
                ldm_x4(base + 0 * PLANEB + a_off[mt] + ko, a[mt]);
            #pragma unroll
            for (int p = 0; p < 4; p++) {
                uint32_t r4[4];
                ldm_x4(base + 1 * PLANEB + b_off[p] + ko, r4);
                bt[2*p][0] = r4[0]; bt[2*p][1] = r4[1];
                bt[2*p+1][0] = r4[2]; bt[2*p+1][1] = r4[3];
            }
            #pragma unroll
            for (int mt = 0; mt < 2; mt++)
                #pragma unroll
                for (int nt = 0; nt < 8; nt++)
                    mma_f16(acc[mt][nt], a[mt], bt[nt]);
        }
    }

    /* epilogue: bias + routing (row-major; dth fused; x fused into lin) */
    int qrow = lane >> 2;
    int qcol = (lane & 3) * 2;
    #pragma unroll
    for (int mt = 0; mt < 2; mt++) {
        #pragma unroll
        for (int half = 0; half < 2; half++) {
            int m = m0 + wm * 32 + mt * 16 + qrow + half * 8;
            #pragma unroll
            for (int nt = 0; nt < 8; nt++) {
                int col = n0 + wn * 64 + nt * 8 + qcol;
                if (col >= NCAT) continue;
                float v0 = acc[mt][nt][half * 2 + 0] + g_bcat[col];
                float v1 = acc[mt][nt][half * 2 + 1] + g_bcat[col + 1];
                if (col < 1024) {
                    float2 hv = *reinterpret_cast<const float2*>(g_h + (size_t)m * Dq + col);
                    float sp0 = softplus_f(v0), sp1 = softplus_f(v1);
                    *reinterpret_cast<float2*>(g_delta + (size_t)m * Dq + col) =
                        make_float2(sp0, sp1);
                    *reinterpret_cast<float2*>(g_dth + (size_t)m * Dq + col) =
                        make_float2(sp0 * hv.x, sp1 * hv.y);
                } else if (col < 2048) {
                    int cc = col - 1024;
                    float2 xr = *reinterpret_cast<const float2*>(xres + (size_t)m * Dq + cc);
                    *reinterpret_cast<float2*>(g_lin + (size_t)m * Dq + cc) =
                        make_float2(v0 + xr.x, v1 + xr.y);
                } else if (col < 2064) {
                    *reinterpret_cast<float2*>(g_Bc + (size_t)m * Nq + (col - 2048)) =
                        make_float2(v0, v1);
                } else {
                    *reinterpret_cast<float2*>(g_Cc + (size_t)m * Nq + (col - 2064)) =
                        make_float2(v0, v1);
                }
            }
        }
    }
}

/* ====== scan v6: smem-staged tiles, coalesced cp.async loads ====== */
/* block 512 = 32 d x 16 n; grid (32, 4); tile TP=8 timesteps        */
#define TP 8
#define SCAN_TILE 1024   /* floats per buffer: dt 0..255, dth 256.., ll 512.., bn 768.., cn 896.. */

__device__ __forceinline__ float ex2f(float x) {
    float r;
    asm("ex2.approx.f32 %0, %1;" : "=f"(r) : "f"(x));
    return r;
}

__device__ __forceinline__ void scan_load_tile(uint32_t sbase, int buf, int t0,
                                               int b, int d0, int tid)
{
    #pragma unroll
    for (int u = 0; u < 2; u++) {
        int task = tid + u * 512;
        const float* src;
        if (task < 768) {
            int arr = task >> 8;            /* 0 dt, 1 dth, 2 lin */
            int t   = (task >> 5) & 7;
            int dl  = task & 31;
            size_t gidx = ((size_t)(b * Sq + t0 + t)) * Dq + d0 + dl;
            src = (arr == 0 ? g_delta : (arr == 1 ? g_dth : g_lin)) + gidx;
        } else {
            int arr = (task >> 7) & 1;      /* 0 Bc, 1 Cc */
            int t   = (task >> 4) & 7;
            int n   = task & 15;
            size_t gidx = ((size_t)(b * Sq + t0 + t)) * Nq + n;
            src = (arr == 0 ? g_Bc : g_Cc) + gidx;
        }
        cp4(sbase + (uint32_t)(buf * SCAN_TILE + task) * 4u, src);
    }
}

__global__ __launch_bounds__(512)
void scan_kernel(float* __restrict__ out)
{
    __shared__ __align__(16) float smem[2 * SCAN_TILE];   /* 8 KB */
    uint32_t sbase = smem_u32(smem);

    int b   = blockIdx.y;
    int tid = threadIdx.x;          /* 512 = 32 d x 16 n */
    int n   = tid & 15;
    int dl  = tid >> 4;             /* 0..31 */
    int d0  = blockIdx.x * 32;
    int d   = d0 + dl;

    float a2 = g_A2[d * Nq + n];
    float s  = 0.f;

    float* outp = out + (size_t)b * Sq * Dq + d;

    scan_load_tile(sbase, 0, 0, b, d0, tid);
    cp_commit();

    const int NT = Sq / TP;          /* 512 */
    for (int j = 0; j < NT; j++) {
        int buf = j & 1;
        int t0  = j * TP;

        __syncthreads();             /* compute(j-1) done before load(j+1) overwrites */
        if (j + 1 < NT) {
            scan_load_tile(sbase, buf ^ 1, t0 + TP, b, d0, tid);
            cp_commit();
            cp_wait<1>();
        } else {
            cp_wait<0>();
        }
        __syncthreads();             /* tile j visible */

        const float* sb = smem + buf * SCAN_TILE;
        /* phase 1: recurrence */
        float pv[TP];
        #pragma unroll
        for (int k = 0; k < TP; k++) {
            float dt = sb[k * 32 + dl];
            float dh = sb[256 + k * 32 + dl];
            float bn = sb[768 + k * 16 + n];
            float dA = ex2f(dt * a2);
            s = fmaf(dA, s, dh * bn);
            pv[k] = s * sb[896 + k * 16 + n];
        }

        /* phase 2: batched butterflies over n (xor 1,2,4,8) */
        #pragma unroll
        for (int o = 1; o <= 8; o <<= 1) {
            float sh[TP];
            #pragma unroll
            for (int k = 0; k < TP; k++)
                sh[k] = __shfl_xor_sync(0xffffffffu, pv[k], o);
            #pragma unroll
            for (int k = 0; k < TP; k++)
                pv[k] += sh[k];
        }

        if (n == 0) {
            #pragma unroll
            for (int k = 0; k < TP; k++)
                outp[(size_t)(t0 + k) * Dq] = sb[512 + k * 32 + dl] + pv[k];
        }
    }
}

/* ------------------------------- launch ------------------------------- */
extern "C" void kernel_launch(void* const* d_in, const int* in_sizes, int n_in,
                              void* d_out, int out_size)
{
    const float* x    = (const float*)d_in[0];
    const float* logA = (const float*)d_in[1];
    const float* Wd   = (const float*)d_in[2];
    const float* bd   = (const float*)d_in[3];
    const float* Wb   = (const float*)d_in[4];
    const float* bb   = (const float*)d_in[5];
    const float* Wc   = (const float*)d_in[6];
    const float* bc   = (const float*)d_in[7];
    const float* WDp  = (const float*)d_in[8];
    const float* bD   = (const float*)d_in[9];
    const float* lnw  = (const float*)d_in[10];
    const float* lnb  = (const float*)d_in[11];
    float* out = (float*)d_out;

    cudaFuncSetAttribute(gemm_hmma_kernel,
                         cudaFuncAttributeMaxDynamicSharedMemorySize, GSMEM);

    prep_kernel<<<NPAD, 256>>>(logA, Wd, bd, Wb, bb, Wc, bc, WDp, bD);
    ln_kernel<<<Mq, 256>>>(x, lnw, lnb);
    dim3 ggrid(NPAD / 128, Mq / 128);            /* 17 x 128 */
    gemm_hmma_kernel<<<ggrid, 256, GSMEM>>>(x);
    dim3 sgrid(Dq / 32, Bq);                     /* 32 x 4 */
    scan_kernel<<<sgrid, 512>>>(out);
}

// round 15
// speedup vs baseline: 1.7184x; 1.1674x over previous
#include <cuda_runtime.h>
#include <cuda_fp16.h>
#include <math.h>
#include <stdint.h>

#define Bq 4
#define Sq 4096
#define Dq 1024
#define Nq 16
#define Mq (Bq*Sq)      /* 16384 rows */
#define Kq Dq           /* 1024 */
#define NCAT 2080
#define NPAD 2176       /* 17*128 */

/* ---- scratch (row-major: coalesced across lanes) ---- */
__device__ float g_h[Mq * Dq];
__device__ float g_dtdh[Mq * Dq * 2];  /* {softplus, softplus*h} pairs */
__device__ float g_lin[Mq * Dq];       /* h@WD + bD + x */
__device__ float g_bc[Mq * Nq * 2];    /* {B, C} pairs */
__device__ float g_bcat[NPAD];
__device__ float g_A2[Dq * Nq];
__device__ __half g_hh[Mq * Kq];
__device__ __half g_Wh[NPAD * Kq];

__device__ __forceinline__ uint32_t smem_u32(const void* p) {
    uint32_t r;
    asm("{ .reg .u64 t; cvta.to.shared.u64 t, %1; cvt.u32.u64 %0, t; }" : "=r"(r) : "l"(p));
    return r;
}

/* ---------------- prep ---------------- */
__global__ void prep_kernel(const float* __restrict__ logA,
                            const float* __restrict__ Wd, const float* __restrict__ bd,
                            const float* __restrict__ Wb, const float* __restrict__ bb,
                            const float* __restrict__ Wc, const float* __restrict__ bc,
                            const float* __restrict__ WD, const float* __restrict__ bD)
{
    int r = blockIdx.x;
    int tid = threadIdx.x;       /* 256 */
    const float* src = 0;
    if (r < 1024)        src = Wd + (size_t)r * Kq;
    else if (r < 2048)   src = WD + (size_t)(r - 1024) * Kq;
    else if (r < 2064)   src = Wb + (size_t)(r - 2048) * Kq;
    else if (r < NCAT)   src = Wc + (size_t)(r - 2064) * Kq;

    float4 v = src ? reinterpret_cast<const float4*>(src)[tid]
                   : make_float4(0.f, 0.f, 0.f, 0.f);
    __half q[4];
    q[0] = __float2half_rn(v.x); q[1] = __float2half_rn(v.y);
    q[2] = __float2half_rn(v.z); q[3] = __float2half_rn(v.w);
    *reinterpret_cast<uint2*>(g_Wh + (size_t)r * Kq + tid * 4) = *reinterpret_cast<uint2*>(q);

    if (tid == 0) {
        float bv = 0.f;
        if (r < 1024)      bv = bd[r];
        else if (r < 2048) bv = bD[r - 1024];
        else if (r < 2064) bv = bb[r - 2048];
        else if (r < NCAT) bv = bc[r - 2064];
        g_bcat[r] = bv;
    }
    if (r < Dq && tid < Nq) {
        g_A2[r * Nq + tid] = -expf(logA[r * Nq + tid]) * 1.44269504088896340736f;
    }
}

/* ---------------- layernorm: fp32 out + fp16 out ---------------- */
__global__ void ln_kernel(const float* __restrict__ x,
                          const float* __restrict__ w,
                          const float* __restrict__ b)
{
    int row = blockIdx.x;
    int tid = threadIdx.x;       /* 256 */
    const float4* x4 = reinterpret_cast<const float4*>(x) + (size_t)row * 256;
    float4 v = x4[tid];
    float sum = v.x + v.y + v.z + v.w;
    float sq  = v.x*v.x + v.y*v.y + v.z*v.z + v.w*v.w;

    #pragma unroll
    for (int o = 16; o > 0; o >>= 1) {
        sum += __shfl_down_sync(0xffffffffu, sum, o);
        sq  += __shfl_down_sync(0xffffffffu, sq, o);
    }
    __shared__ float red0[8], red1[8];
    int warp = tid >> 5, lane = tid & 31;
    if (lane == 0) { red0[warp] = sum; red1[warp] = sq; }
    __syncthreads();
    if (tid < 32) {
        float s1 = (tid < 8) ? red0[tid] : 0.f;
        float s2 = (tid < 8) ? red1[tid] : 0.f;
        #pragma unroll
        for (int o = 4; o > 0; o >>= 1) {
            s1 += __shfl_down_sync(0xffffffffu, s1, o);
            s2 += __shfl_down_sync(0xffffffffu, s2, o);
        }
        if (tid == 0) { red0[0] = s1; red1[0] = s2; }
    }
    __syncthreads();
    float mean = red0[0] * (1.0f / Dq);
    float var  = red1[0] * (1.0f / Dq) - mean * mean;
    float rs   = rsqrtf(var + 1e-5f);

    float4 wv = reinterpret_cast<const float4*>(w)[tid];
    float4 bv = reinterpret_cast<const float4*>(b)[tid];
    float4 o;
    o.x = (v.x - mean) * rs * wv.x + bv.x;
    o.y = (v.y - mean) * rs * wv.y + bv.y;
    o.z = (v.z - mean) * rs * wv.z + bv.z;
    o.w = (v.w - mean) * rs * wv.w + bv.w;
    reinterpret_cast<float4*>(g_h)[(size_t)row * 256 + tid] = o;

    __half q[4];
    q[0] = __float2half_rn(o.x); q[1] = __float2half_rn(o.y);
    q[2] = __float2half_rn(o.z); q[3] = __float2half_rn(o.w);
    *reinterpret_cast<uint2*>(g_hh + (size_t)row * Kq + tid * 4) = *reinterpret_cast<uint2*>(q);
}

/* ====== HMMA GEMM: fp16 1-term, BK=32, 3-stage, 2 CTAs/SM ====== */
#define BK5 32
#define KPADB 80
#define PLANEB (128 * KPADB)
#define STAGEB (2 * PLANEB)
#define NSTG 3
#define GSMEM (NSTG * STAGEB)     /* 61440 B */
#define NCHK5 (Kq / BK5)          /* 32 */

__device__ __forceinline__ void cp16(uint32_t dst, const void* src) {
    asm volatile("cp.async.cg.shared.global [%0], [%1], 16;" :: "r"(dst), "l"(src) : "memory");
}
__device__ __forceinline__ void cp_commit() {
    asm volatile("cp.async.commit_group;" ::: "memory");
}
template<int N> __device__ __forceinline__ void cp_wait() {
    asm volatile("cp.async.wait_group %0;" :: "n"(N) : "memory");
}
__device__ __forceinline__ void ldm_x4(uint32_t addr, uint32_t* r) {
    asm volatile("ldmatrix.sync.aligned.m8n8.x4.shared.b16 {%0,%1,%2,%3}, [%4];"
                 : "=r"(r[0]), "=r"(r[1]), "=r"(r[2]), "=r"(r[3]) : "r"(addr));
}
__device__ __forceinline__ void mma_f16(float* c, const uint32_t* a, const uint32_t* b) {
    asm volatile("mma.sync.aligned.m16n8k16.row.col.f32.f16.f16.f32 "
                 "{%0,%1,%2,%3}, {%4,%5,%6,%7}, {%8,%9}, {%0,%1,%2,%3};"
                 : "+f"(c[0]), "+f"(c[1]), "+f"(c[2]), "+f"(c[3])
                 : "r"(a[0]), "r"(a[1]), "r"(a[2]), "r"(a[3]), "r"(b[0]), "r"(b[1]));
}
__device__ __forceinline__ float softplus_f(float v) {
    return fmaxf(v, 0.f) + log1pf(expf(-fabsf(v)));
}

__device__ __forceinline__ void fill_stage(uint32_t sbase, int kc, int tid,
                                           const __half* A, const __half* B)
{
    const __half* srcs[2] = {A, B};
    #pragma unroll
    for (int p = 0; p < 2; p++) {
        #pragma unroll
        for (int i = 0; i < 2; i++) {
            int id = tid + i * 256;
            int row = id >> 2, q = id & 3;
            cp16(sbase + p * PLANEB + row * KPADB + q * 16,
                 srcs[p] + (size_t)row * Kq + kc * BK5 + q * 8);
        }
    }
}

__global__ __launch_bounds__(256, 2)
void gemm_hmma_kernel(const float* __restrict__ xres)
{
    extern __shared__ __align__(16) char dynsm[];
    uint32_t smb = smem_u32(dynsm);

    int tid  = threadIdx.x;
    int wid  = tid >> 5, lane = tid & 31;
    int n0   = blockIdx.x * 128;
    int m0   = blockIdx.y * 128;
    int wm   = wid >> 1;
    int wn   = wid & 1;

    const __half* Ah = g_hh + (size_t)m0 * Kq;
    const __half* Bh = g_Wh + (size_t)n0 * Kq;

    float acc[2][8][4];
    #pragma unroll
    for (int i = 0; i < 2; i++)
        #pragma unroll
        for (int j = 0; j < 8; j++)
            #pragma unroll
            for (int k = 0; k < 4; k++) acc[i][j][k] = 0.f;

    uint32_t a_off[2], b_off[8];
    #pragma unroll
    for (int mt = 0; mt < 2; mt++)
        a_off[mt] = (uint32_t)((wm * 32 + (lane & 15) + mt * 16) * KPADB + (lane >> 4) * 16);
    #pragma unroll
    for (int p = 0; p < 4; p++)
        b_off[p] = (uint32_t)((wn * 64 + (lane & 7) + ((lane >> 4) * 8) + p * 16) * KPADB
                              + ((lane >> 3) & 1) * 16);

    fill_stage(smb + 0 * STAGEB, 0, tid, Ah, Bh); cp_commit();
    fill_stage(smb + 1 * STAGEB, 1, tid, Ah, Bh); cp_commit();

    for (int kc = 0; kc < NCHK5; kc++) {
        int buf = kc % NSTG;
        if (kc == NCHK5 - 1) cp_wait<0>(); else cp_wait<1>();
        __syncthreads();
        if (kc + 2 < NCHK5) {
            fill_stage(smb + ((kc + 2) % NSTG) * STAGEB, kc + 2, tid, Ah, Bh);
            cp_commit();
        }

        uint32_t base = smb + buf * STAGEB;
        #pragma unroll
        for (int kk = 0; kk < 2; kk++) {
            uint32_t ko = (uint32_t)(kk * 32);
            uint32_t a[2][4], bt[8][2];
            #pragma unroll
            for (int mt = 0; mt < 2; mt++)
                ldm_x4(base + 0 * PLANEB + a_off[mt] + ko, a[mt]);
            #pragma unroll
            for (int p = 0; p < 4; p++) {
                uint32_t r4[4];
                ldm_x4(base + 1 * PLANEB + b_off[p] + ko, r4);
                bt[2*p][0] = r4[0]; bt[2*p][1] = r4[1];
                bt[2*p+1][0] = r4[2]; bt[2*p+1][1] = r4[3];
            }
            #pragma unroll
            for (int mt = 0; mt < 2; mt++)
                #pragma unroll
                for (int nt = 0; nt < 8; nt++)
                    mma_f16(acc[mt][nt], a[mt], bt[nt]);
        }
    }

    /* epilogue: bias + routing (packed pairs; x fused into lin) */
    int qrow = lane >> 2;
    int qcol = (lane & 3) * 2;
    #pragma unroll
    for (int mt = 0; mt < 2; mt++) {
        #pragma unroll
        for (int half = 0; half < 2; half++) {
            int m = m0 + wm * 32 + mt * 16 + qrow + half * 8;
            #pragma unroll
            for (int nt = 0; nt < 8; nt++) {
                int col = n0 + wn * 64 + nt * 8 + qcol;
                if (col >= NCAT) continue;
                float v0 = acc[mt][nt][half * 2 + 0] + g_bcat[col];
                float v1 = acc[mt][nt][half * 2 + 1] + g_bcat[col + 1];
                if (col < 1024) {
                    float2 hv = *reinterpret_cast<const float2*>(g_h + (size_t)m * Dq + col);
                    float sp0 = softplus_f(v0), sp1 = softplus_f(v1);
                    float4 o4 = make_float4(sp0, sp0 * hv.x, sp1, sp1 * hv.y);
                    *reinterpret_cast<float4*>(g_dtdh + ((size_t)m * Dq + col) * 2) = o4;
                } else if (col < 2048) {
                    int cc = col - 1024;
                    float2 xr = *reinterpret_cast<const float2*>(xres + (size_t)m * Dq + cc);
                    *reinterpret_cast<float2*>(g_lin + (size_t)m * Dq + cc) =
                        make_float2(v0 + xr.x, v1 + xr.y);
                } else if (col < 2064) {
                    int cc = col - 2048;
                    g_bc[((size_t)m * Nq + cc) * 2]     = v0;
                    g_bc[((size_t)m * Nq + cc + 1) * 2] = v1;
                } else {
                    int cc = col - 2064;
                    g_bc[((size_t)m * Nq + cc) * 2 + 1]     = v0;
                    g_bc[((size_t)m * Nq + cc + 1) * 2 + 1] = v1;
                }
            }
        }
    }
}

/* ====== scan v7: packed pairs, TP=16, select-tree outputs ====== */
/* block 512 = 32 d x 16 n; grid (32, 4)                            */
#define TP 16
#define DTDH_OFF 0        /* [16t][64]  = 1024 floats */
#define LL_OFF   1024     /* [16t][36]  =  576 floats (padded rows) */
#define BC_OFF   1600     /* [16t][32]  =  512 floats */
#define BUFSZ    2112

__device__ __forceinline__ void cp4_ca(uint32_t dst, const void* src) {
    asm volatile("cp.async.ca.shared.global [%0], [%1], 16;" :: "r"(dst), "l"(src) : "memory");
}
__device__ __forceinline__ float ex2f(float x) {
    float r;
    asm("ex2.approx.f32 %0, %1;" : "=f"(r) : "f"(x));
    return r;
}

__device__ __forceinline__ void scan_load_tile(uint32_t sbase, int buf, int t0,
                                               int b, int d0, int tid)
{
    /* 512 cp.async(16B) tasks: dtdh 256, ll 128, bc 128 */
    const float* src;
    uint32_t doff;
    if (tid < 256) {
        int t = tid >> 4, j = tid & 15;
        src  = g_dtdh + ((size_t)(b * Sq + t0 + t) * Dq + d0) * 2 + j * 4;
        doff = (uint32_t)(DTDH_OFF + t * 64 + j * 4);
    } else if (tid < 384) {
        int idx = tid - 256;
        int t = idx >> 3, j = idx & 7;
        src  = g_lin + (size_t)(b * Sq + t0 + t) * Dq + d0 + j * 4;
        doff = (uint32_t)(LL_OFF + t * 36 + j * 4);
    } else {
        int idx = tid - 384;
        int t = idx >> 3, j = idx & 7;
        src  = g_bc + (size_t)(b * Sq + t0 + t) * (Nq * 2) + j * 4;
        doff = (uint32_t)(BC_OFF + t * 32 + j * 4);
    }
    cp4_ca(sbase + (uint32_t)(buf * BUFSZ) * 4u + doff * 4u, src);
}

__global__ __launch_bounds__(512)
void scan_kernel(float* __restrict__ out)
{
    __shared__ __align__(16) float smem[2 * BUFSZ];   /* 16.9 KB */
    uint32_t sbase = smem_u32(smem);

    int b   = blockIdx.y;
    int tid = threadIdx.x;          /* 512 = 32 d x 16 n */
    int n   = tid & 15;
    int dl  = tid >> 4;             /* 0..31 */
    int d0  = blockIdx.x * 32;
    int d   = d0 + dl;

    float a2 = g_A2[d * Nq + n];
    float s  = 0.f;

    scan_load_tile(sbase, 0, 0, b, d0, tid);
    cp_commit();

    const int NT = Sq / TP;          /* 256 */
    for (int j = 0; j < NT; j++) {
        int buf = j & 1;
        int t0  = j * TP;

        __syncthreads();
        if (j + 1 < NT) {
            scan_load_tile(sbase, buf ^ 1, t0 + TP, b, d0, tid);
            cp_commit();
            cp_wait<1>();
        } else {
            cp_wait<0>();
        }
        __syncthreads();

        const float* sb = smem + buf * BUFSZ;

        /* phase 1: recurrence */
        float pv[TP];
        #pragma unroll
        for (int k = 0; k < TP; k++) {
            float2 dd  = *reinterpret_cast<const float2*>(sb + DTDH_OFF + k * 64 + dl * 2);
            float2 bcv = *reinterpret_cast<const float2*>(sb + BC_OFF + k * 32 + n * 2);
            float dA = ex2f(dd.x * a2);
            s = fmaf(dA, s, dd.y * bcv.x);
            pv[k] = s * bcv.y;
        }

        /* phase 2: batched butterflies over n */
        #pragma unroll
        for (int o = 1; o <= 8; o <<= 1) {
            float sh[TP];
            #pragma unroll
            for (int k = 0; k < TP; k++)
                sh[k] = __shfl_xor_sync(0xffffffffu, pv[k], o);
            #pragma unroll
            for (int k = 0; k < TP; k++)
                pv[k] += sh[k];
        }

        /* select-tree: lane n picks pv[n]; all 512 threads write one output */
        float s1[8], s2[4], s3[2], v;
        #pragma unroll
        for (int q = 0; q < 8; q++) s1[q] = (n & 1) ? pv[2*q+1] : pv[2*q];
        #pragma unroll
        for (int q = 0; q < 4; q++) s2[q] = (n & 2) ? s1[2*q+1] : s1[2*q];
        #pragma unroll
        for (int q = 0; q < 2; q++) s3[q] = (n & 4) ? s2[2*q+1] : s2[2*q];
        v = (n & 8) ? s3[1] : s3[0];

        out[(size_t)(b * Sq + t0 + n) * Dq + d] = sb[LL_OFF + n * 36 + dl] + v;
    }
}

/* ------------------------------- launch ------------------------------- */
extern "C" void kernel_launch(void* const* d_in, const int* in_sizes, int n_in,
                              void* d_out, int out_size)
{
    const float* x    = (const float*)d_in[0];
    const float* logA = (const float*)d_in[1];
    const float* Wd   = (const float*)d_in[2];
    const float* bd   = (const float*)d_in[3];
    const float* Wb   = (const float*)d_in[4];
    const float* bb   = (const float*)d_in[5];
    const float* Wc   = (const float*)d_in[6];
    const float* bc   = (const float*)d_in[7];
    const float* WDp  = (const float*)d_in[8];
    const float* bD   = (const float*)d_in[9];
    const float* lnw  = (const float*)d_in[10];
    const float* lnb  = (const float*)d_in[11];
    float* out = (float*)d_out;

    cudaFuncSetAttribute(gemm_hmma_kernel,
                         cudaFuncAttributeMaxDynamicSharedMemorySize, GSMEM);

    prep_kernel<<<NPAD, 256>>>(logA, Wd, bd, Wb, bb, Wc, bc, WDp, bD);
    ln_kernel<<<Mq, 256>>>(x, lnw, lnb);
    dim3 ggrid(NPAD / 128, Mq / 128);            /* 17 x 128 */
    gemm_hmma_kernel<<<ggrid, 256, GSMEM>>>(x);
    dim3 sgrid(Dq / 32, Bq);                     /* 32 x 4 */
    scan_kernel<<<sgrid, 512>>>(out);
}

// round 16
// speedup vs baseline: 1.8465x; 1.0746x over previous
#include <cuda_runtime.h>
#include <cuda_fp16.h>
#include <math.h>
#include <stdint.h>

#define Bq 4
#define Sq 4096
#define Dq 1024
#define Nq 16
#define Mq (Bq*Sq)      /* 16384 rows */
#define Kq Dq           /* 1024 */
#define NCAT 2080
#define NPAD 2176       /* 17*128 */

/* ---- scratch (row-major: coalesced across lanes) ---- */
__device__ float g_h[Mq * Dq];
__device__ float g_dtdh[Mq * Dq * 2];  /* {softplus, softplus*h} pairs */
__device__ float g_lin[Mq * Dq];       /* h@WD + bD + x */
__device__ float g_bc[Mq * Nq * 2];    /* {B, C} pairs */
__device__ float g_bcat[NPAD];
__device__ float g_A2[Dq * Nq];
__device__ __half g_hh[Mq * Kq];
__device__ __half g_Wh[NPAD * Kq];

__device__ __forceinline__ uint32_t smem_u32(const void* p) {
    uint32_t r;
    asm("{ .reg .u64 t; cvta.to.shared.u64 t, %1; cvt.u32.u64 %0, t; }" : "=r"(r) : "l"(p));
    return r;
}

/* ---------------- prep ---------------- */
__global__ void prep_kernel(const float* __restrict__ logA,
                            const float* __restrict__ Wd, const float* __restrict__ bd,
                            const float* __restrict__ Wb, const float* __restrict__ bb,
                            const float* __restrict__ Wc, const float* __restrict__ bc,
                            const float* __restrict__ WD, const float* __restrict__ bD)
{
    int r = blockIdx.x;
    int tid = threadIdx.x;       /* 256 */
    const float* src = 0;
    if (r < 1024)        src = Wd + (size_t)r * Kq;
    else if (r < 2048)   src = WD + (size_t)(r - 1024) * Kq;
    else if (r < 2064)   src = Wb + (size_t)(r - 2048) * Kq;
    else if (r < NCAT)   src = Wc + (size_t)(r - 2064) * Kq;

    float4 v = src ? reinterpret_cast<const float4*>(src)[tid]
                   : make_float4(0.f, 0.f, 0.f, 0.f);
    __half q[4];
    q[0] = __float2half_rn(v.x); q[1] = __float2half_rn(v.y);
    q[2] = __float2half_rn(v.z); q[3] = __float2half_rn(v.w);
    *reinterpret_cast<uint2*>(g_Wh + (size_t)r * Kq + tid * 4) = *reinterpret_cast<uint2*>(q);

    if (tid == 0) {
        float bv = 0.f;
        if (r < 1024)      bv = bd[r];
        else if (r < 2048) bv = bD[r - 1024];
        else if (r < 2064) bv = bb[r - 2048];
        else if (r < NCAT) bv = bc[r - 2064];
        g_bcat[r] = bv;
    }
    if (r < Dq && tid < Nq) {
        g_A2[r * Nq + tid] = -expf(logA[r * Nq + tid]) * 1.44269504088896340736f;
    }
}

/* ---------------- layernorm: fp32 out + fp16 out ---------------- */
__global__ void ln_kernel(const float* __restrict__ x,
                          const float* __restrict__ w,
                          const float* __restrict__ b)
{
    int row = blockIdx.x;
    int tid = threadIdx.x;       /* 256 */
    const float4* x4 = reinterpret_cast<const float4*>(x) + (size_t)row * 256;
    float4 v = x4[tid];
    float sum = v.x + v.y + v.z + v.w;
    float sq  = v.x*v.x + v.y*v.y + v.z*v.z + v.w*v.w;

    #pragma unroll
    for (int o = 16; o > 0; o >>= 1) {
        sum += __shfl_down_sync(0xffffffffu, sum, o);
        sq  += __shfl_down_sync(0xffffffffu, sq, o);
    }
    __shared__ float red0[8], red1[8];
    int warp = tid >> 5, lane = tid & 31;
    if (lane == 0) { red0[warp] = sum; red1[warp] = sq; }
    __syncthreads();
    if (tid < 32) {
        float s1 = (tid < 8) ? red0[tid] : 0.f;
        float s2 = (tid < 8) ? red1[tid] : 0.f;
        #pragma unroll
        for (int o = 4; o > 0; o >>= 1) {
            s1 += __shfl_down_sync(0xffffffffu, s1, o);
            s2 += __shfl_down_sync(0xffffffffu, s2, o);
        }
        if (tid == 0) { red0[0] = s1; red1[0] = s2; }
    }
    __syncthreads();
    float mean = red0[0] * (1.0f / Dq);
    float var  = red1[0] * (1.0f / Dq) - mean * mean;
    float rs   = rsqrtf(var + 1e-5f);

    float4 wv = reinterpret_cast<const float4*>(w)[tid];
    float4 bv = reinterpret_cast<const float4*>(b)[tid];
    float4 o;
    o.x = (v.x - mean) * rs * wv.x + bv.x;
    o.y = (v.y - mean) * rs * wv.y + bv.y;
    o.z = (v.z - mean) * rs * wv.z + bv.z;
    o.w = (v.w - mean) * rs * wv.w + bv.w;
    reinterpret_cast<float4*>(g_h)[(size_t)row * 256 + tid] = o;

    __half q[4];
    q[0] = __float2half_rn(o.x); q[1] = __float2half_rn(o.y);
    q[2] = __float2half_rn(o.z); q[3] = __float2half_rn(o.w);
    *reinterpret_cast<uint2*>(g_hh + (size_t)row * Kq + tid * 4) = *reinterpret_cast<uint2*>(q);
}

/* ====== HMMA GEMM: fp16 1-term, BK=32, 3-stage, 2 CTAs/SM ====== */
#define BK5 32
#define KPADB 80
#define PLANEB (128 * KPADB)
#define STAGEB (2 * PLANEB)
#define NSTG 3
#define GSMEM (NSTG * STAGEB)     /* 61440 B */
#define NCHK5 (Kq / BK5)          /* 32 */

__device__ __forceinline__ void cp16(uint32_t dst, const void* src) {
    asm volatile("cp.async.cg.shared.global [%0], [%1], 16;" :: "r"(dst), "l"(src) : "memory");
}
__device__ __forceinline__ void cp_commit() {
    asm volatile("cp.async.commit_group;" ::: "memory");
}
template<int N> __device__ __forceinline__ void cp_wait() {
    asm volatile("cp.async.wait_group %0;" :: "n"(N) : "memory");
}
__device__ __forceinline__ void ldm_x4(uint32_t addr, uint32_t* r) {
    asm volatile("ldmatrix.sync.aligned.m8n8.x4.shared.b16 {%0,%1,%2,%3}, [%4];"
                 : "=r"(r[0]), "=r"(r[1]), "=r"(r[2]), "=r"(r[3]) : "r"(addr));
}
__device__ __forceinline__ void mma_f16(float* c, const uint32_t* a, const uint32_t* b) {
    asm volatile("mma.sync.aligned.m16n8k16.row.col.f32.f16.f16.f32 "
                 "{%0,%1,%2,%3}, {%4,%5,%6,%7}, {%8,%9}, {%0,%1,%2,%3};"
                 : "+f"(c[0]), "+f"(c[1]), "+f"(c[2]), "+f"(c[3])
                 : "r"(a[0]), "r"(a[1]), "r"(a[2]), "r"(a[3]), "r"(b[0]), "r"(b[1]));
}
__device__ __forceinline__ float softplus_f(float v) {
    return fmaxf(v, 0.f) + log1pf(expf(-fabsf(v)));
}

__device__ __forceinline__ void fill_stage(uint32_t sbase, int kc, int tid,
                                           const __half* A, const __half* B)
{
    const __half* srcs[2] = {A, B};
    #pragma unroll
    for (int p = 0; p < 2; p++) {
        #pragma unroll
        for (int i = 0; i < 2; i++) {
            int id = tid + i * 256;
            int row = id >> 2, q = id & 3;
            cp16(sbase + p * PLANEB + row * KPADB + q * 16,
                 srcs[p] + (size_t)row * Kq + kc * BK5 + q * 8);
        }
    }
}

__global__ __launch_bounds__(256, 2)
void gemm_hmma_kernel(const float* __restrict__ xres)
{
    extern __shared__ __align__(16) char dynsm[];
    uint32_t smb = smem_u32(dynsm);

    int tid  = threadIdx.x;
    int wid  = tid >> 5, lane = tid & 31;
    int n0   = blockIdx.x * 128;
    int m0   = blockIdx.y * 128;
    int wm   = wid >> 1;
    int wn   = wid & 1;

    const __half* Ah = g_hh + (size_t)m0 * Kq;
    const __half* Bh = g_Wh + (size_t)n0 * Kq;

    float acc[2][8][4];
    #pragma unroll
    for (int i = 0; i < 2; i++)
        #pragma unroll
        for (int j = 0; j < 8; j++)
            #pragma unroll
            for (int k = 0; k < 4; k++) acc[i][j][k] = 0.f;

    uint32_t a_off[2], b_off[8];
    #pragma unroll
    for (int mt = 0; mt < 2; mt++)
        a_off[mt] = (uint32_t)((wm * 32 + (lane & 15) + mt * 16) * KPADB + (lane >> 4) * 16);
    #pragma unroll
    for (int p = 0; p < 4; p++)
        b_off[p] = (uint32_t)((wn * 64 + (lane & 7) + ((lane >> 4) * 8) + p * 16) * KPADB
                              + ((lane >> 3) & 1) * 16);

    fill_stage(smb + 0 * STAGEB, 0, tid, Ah, Bh); cp_commit();
    fill_stage(smb + 1 * STAGEB, 1, tid, Ah, Bh); cp_commit();

    for (int kc = 0; kc < NCHK5; kc++) {
        int buf = kc % NSTG;
        if (kc == NCHK5 - 1) cp_wait<0>(); else cp_wait<1>();
        __syncthreads();
        if (kc + 2 < NCHK5) {
            fill_stage(smb + ((kc + 2) % NSTG) * STAGEB, kc + 2, tid, Ah, Bh);
            cp_commit();
        }

        uint32_t base = smb + buf * STAGEB;
        #pragma unroll
        for (int kk = 0; kk < 2; kk++) {
            uint32_t ko = (uint32_t)(kk * 32);
            uint32_t a[2][4], bt[8][2];
            #pragma unroll
            for (int mt = 0; mt < 2; mt++)
                ldm_x4(base + 0 * PLANEB + a_off[mt] + ko, a[mt]);
            #pragma unroll
            for (int p = 0; p < 4; p++) {
                uint32_t r4[4];
                ldm_x4(base + 1 * PLANEB + b_off[p] + ko, r4);
                bt[2*p][0] = r4[0]; bt[2*p][1] = r4[1];
                bt[2*p+1][0] = r4[2]; bt[2*p+1][1] = r4[3];
            }
            #pragma unroll
            for (int mt = 0; mt < 2; mt++)
                #pragma unroll
                for (int nt = 0; nt < 8; nt++)
                    mma_f16(acc[mt][nt], a[mt], bt[nt]);
        }
    }

    /* epilogue: bias + routing (packed pairs; x fused into lin) */
    int qrow = lane >> 2;
    int qcol = (lane & 3) * 2;
    #pragma unroll
    for (int mt = 0; mt < 2; mt++) {
        #pragma unroll
        for (int half = 0; half < 2; half++) {
            int m = m0 + wm * 32 + mt * 16 + qrow + half * 8;
            #pragma unroll
            for (int nt = 0; nt < 8; nt++) {
                int col = n0 + wn * 64 + nt * 8 + qcol;
                if (col >= NCAT) continue;
                float v0 = acc[mt][nt][half * 2 + 0] + g_bcat[col];
                float v1 = acc[mt][nt][half * 2 + 1] + g_bcat[col + 1];
                if (col < 1024) {
                    float2 hv = *reinterpret_cast<const float2*>(g_h + (size_t)m * Dq + col);
                    float sp0 = softplus_f(v0), sp1 = softplus_f(v1);
                    float4 o4 = make_float4(sp0, sp0 * hv.x, sp1, sp1 * hv.y);
                    *reinterpret_cast<float4*>(g_dtdh + ((size_t)m * Dq + col) * 2) = o4;
                } else if (col < 2048) {
                    int cc = col - 1024;
                    float2 xr = *reinterpret_cast<const float2*>(xres + (size_t)m * Dq + cc);
                    *reinterpret_cast<float2*>(g_lin + (size_t)m * Dq + cc) =
                        make_float2(v0 + xr.x, v1 + xr.y);
                } else if (col < 2064) {
                    int cc = col - 2048;
                    g_bc[((size_t)m * Nq + cc) * 2]     = v0;
                    g_bc[((size_t)m * Nq + cc + 1) * 2] = v1;
                } else {
                    int cc = col - 2064;
                    g_bc[((size_t)m * Nq + cc) * 2 + 1]     = v0;
                    g_bc[((size_t)m * Nq + cc + 1) * 2 + 1] = v1;
                }
            }
        }
    }
}

/* ====== scan v8: packed pairs, TP=16, transpose-reduce, staged stores ====== */
/* block 512 = 32 d x 16 n; grid (32, 4)                                      */
#define TP 16
#define DTDH_OFF 0        /* [16t][64]  = 1024 floats */
#define LL_OFF   1024     /* [16t][36]  =  576 floats (padded rows) */
#define BC_OFF   1600     /* [16t][32]  =  512 floats */
#define BUFSZ    2112
#define STG_OFF  (2 * BUFSZ)      /* stage: [16t][34] = 544 floats */

__device__ __forceinline__ void cp16_ca(uint32_t dst, const void* src) {
    asm volatile("cp.async.ca.shared.global [%0], [%1], 16;" :: "r"(dst), "l"(src) : "memory");
}
__device__ __forceinline__ float ex2f(float x) {
    float r;
    asm("ex2.approx.f32 %0, %1;" : "=f"(r) : "f"(x));
    return r;
}

__device__ __forceinline__ void scan_load_tile(uint32_t sbase, int buf, int t0,
                                               int b, int d0, int tid)
{
    /* 512 cp.async(16B) tasks: dtdh 256, ll 128, bc 128 */
    const float* src;
    uint32_t doff;
    if (tid < 256) {
        int t = tid >> 4, j = tid & 15;
        src  = g_dtdh + ((size_t)(b * Sq + t0 + t) * Dq + d0) * 2 + j * 4;
        doff = (uint32_t)(DTDH_OFF + t * 64 + j * 4);
    } else if (tid < 384) {
        int idx = tid - 256;
        int t = idx >> 3, j = idx & 7;
        src  = g_lin + (size_t)(b * Sq + t0 + t) * Dq + d0 + j * 4;
        doff = (uint32_t)(LL_OFF + t * 36 + j * 4);
    } else {
        int idx = tid - 384;
        int t = idx >> 3, j = idx & 7;
        src  = g_bc + (size_t)(b * Sq + t0 + t) * (Nq * 2) + j * 4;
        doff = (uint32_t)(BC_OFF + t * 32 + j * 4);
    }
    cp16_ca(sbase + (uint32_t)(buf * BUFSZ) * 4u + doff * 4u, src);
}

__global__ __launch_bounds__(512)
void scan_kernel(float* __restrict__ out)
{
    __shared__ __align__(16) float smem[2 * BUFSZ + 16 * 34];   /* ~19 KB */
    uint32_t sbase = smem_u32(smem);
    float* stage = smem + STG_OFF;

    int b   = blockIdx.y;
    int tid = threadIdx.x;          /* 512 = 32 d x 16 n */
    int n   = tid & 15;
    int dl  = tid >> 4;             /* 0..31 */
    int d0  = blockIdx.x * 32;
    int d   = d0 + dl;

    /* output-store mapping */
    int st_t = tid >> 5;            /* 0..15 */
    int st_d = tid & 31;            /* 0..31 */

    float a2 = g_A2[d * Nq + n];
    float s  = 0.f;

    scan_load_tile(sbase, 0, 0, b, d0, tid);
    cp_commit();

    const int NT = Sq / TP;          /* 256 */
    for (int j = 0; j < NT; j++) {
        int buf = j & 1;
        int t0  = j * TP;

        __syncthreads();
        if (j + 1 < NT) {
            scan_load_tile(sbase, buf ^ 1, t0 + TP, b, d0, tid);
            cp_commit();
            cp_wait<1>();
        } else {
            cp_wait<0>();
        }
        __syncthreads();

        const float* sb = smem + buf * BUFSZ;

        /* phase 1: recurrence */
        float pv[TP];
        #pragma unroll
        for (int k = 0; k < TP; k++) {
            float2 dd  = *reinterpret_cast<const float2*>(sb + DTDH_OFF + k * 64 + dl * 2);
            float2 bcv = *reinterpret_cast<const float2*>(sb + BC_OFF + k * 32 + n * 2);
            float dA = ex2f(dd.x * a2);
            s = fmaf(dA, s, dd.y * bcv.x);
            pv[k] = s * bcv.y;
        }

        /* phase 2: 16x16 in-register lane transpose (within 16-lane groups).
           After: lane n's pv[m] = original lane m's pv[n]. */
        #pragma unroll
        for (int o = 1; o <= 8; o <<= 1) {
            bool up = (n & o) != 0;
            #pragma unroll
            for (int k = 0; k < TP; k++) {
                if (k & o) continue;
                float give = up ? pv[k] : pv[k + o];
                float recv = __shfl_xor_sync(0xffffffffu, give, o);
                if (up) pv[k] = recv; else pv[k + o] = recv;
            }
        }
        /* local sum: thread (dl, n) now owns output for (t = n, d = dl) */
        #pragma unroll
        for (int st = 1; st < TP; st <<= 1)
            #pragma unroll
            for (int k = 0; k < TP; k += 2 * st)
                pv[k] += pv[k + st];

        stage[n * 34 + dl] = pv[0];
        __syncthreads();

        /* coalesced store: warp = 32 contiguous d for fixed t */
        float lv = sb[LL_OFF + st_t * 36 + st_d];
        out[(size_t)(b * Sq + t0 + st_t) * Dq + d0 + st_d] = lv + stage[st_t * 34 + st_d];
    }
}

/* ------------------------------- launch ------------------------------- */
extern "C" void kernel_launch(void* const* d_in, const int* in_sizes, int n_in,
                              void* d_out, int out_size)
{
    const float* x    = (const float*)d_in[0];
    const float* logA = (const float*)d_in[1];
    const float* Wd   = (const float*)d_in[2];
    const float* bd   = (const float*)d_in[3];
    const float* Wb   = (const float*)d_in[4];
    const float* bb   = (const float*)d_in[5];
    const float* Wc   = (const float*)d_in[6];
    const float* bc   = (const float*)d_in[7];
    const float* WDp  = (const float*)d_in[8];
    const float* bD   = (const float*)d_in[9];
    const float* lnw  = (const float*)d_in[10];
    const float* lnb  = (const float*)d_in[11];
    float* out = (float*)d_out;

    cudaFuncSetAttribute(gemm_hmma_kernel,
                         cudaFuncAttributeMaxDynamicSharedMemorySize, GSMEM);

    prep_kernel<<<NPAD, 256>>>(logA, Wd, bd, Wb, bb, Wc, bc, WDp, bD);
    ln_kernel<<<Mq, 256>>>(x, lnw, lnb);
    dim3 ggrid(NPAD / 128, Mq / 128);            /* 17 x 128 */
    gemm_hmma_kernel<<<ggrid, 256, GSMEM>>>(x);
    dim3 sgrid(Dq / 32, Bq);                     /* 32 x 4 */
    scan_kernel<<<sgrid, 512>>>(out);
}

// round 17
// speedup vs baseline: 2.0110x; 1.0891x over previous
#include <cuda_runtime.h>
#include <cuda_fp16.h>
#include <math.h>
#include <stdint.h>

#define Bq 4
#define Sq 4096
#define Dq 1024
#define Nq 16
#define Mq (Bq*Sq)      /* 16384 rows */
#define Kq Dq           /* 1024 */
#define NCAT 2080
#define NPAD 2176       /* 17*128 */

/* ---- scratch (row-major: coalesced across lanes) ---- */
__device__ float g_h[Mq * Dq];
__device__ float g_dtdh[Mq * Dq * 2];  /* {softplus, softplus*h} pairs */
__device__ float g_lin[Mq * Dq];       /* h@WD + bD + x */
__device__ float g_bc[Mq * Nq * 2];    /* {B, C} pairs */
__device__ float g_bcat[NPAD];
__device__ float g_A2[Dq * Nq];
__device__ __half g_hh[Mq * Kq];
__device__ __half g_Wh[NPAD * Kq];

__device__ __forceinline__ uint32_t smem_u32(const void* p) {
    uint32_t r;
    asm("{ .reg .u64 t; cvta.to.shared.u64 t, %1; cvt.u32.u64 %0, t; }" : "=r"(r) : "l"(p));
    return r;
}

/* ---------------- prep ---------------- */
__global__ void prep_kernel(const float* __restrict__ logA,
                            const float* __restrict__ Wd, const float* __restrict__ bd,
                            const float* __restrict__ Wb, const float* __restrict__ bb,
                            const float* __restrict__ Wc, const float* __restrict__ bc,
                            const float* __restrict__ WD, const float* __restrict__ bD)
{
    int r = blockIdx.x;
    int tid = threadIdx.x;       /* 256 */
    const float* src = 0;
    if (r < 1024)        src = Wd + (size_t)r * Kq;
    else if (r < 2048)   src = WD + (size_t)(r - 1024) * Kq;
    else if (r < 2064)   src = Wb + (size_t)(r - 2048) * Kq;
    else if (r < NCAT)   src = Wc + (size_t)(r - 2064) * Kq;

    float4 v = src ? reinterpret_cast<const float4*>(src)[tid]
                   : make_float4(0.f, 0.f, 0.f, 0.f);
    __half q[4];
    q[0] = __float2half_rn(v.x); q[1] = __float2half_rn(v.y);
    q[2] = __float2half_rn(v.z); q[3] = __float2half_rn(v.w);
    *reinterpret_cast<uint2*>(g_Wh + (size_t)r * Kq + tid * 4) = *reinterpret_cast<uint2*>(q);

    if (tid == 0) {
        float bv = 0.f;
        if (r < 1024)      bv = bd[r];
        else if (r < 2048) bv = bD[r - 1024];
        else if (r < 2064) bv = bb[r - 2048];
        else if (r < NCAT) bv = bc[r - 2064];
        g_bcat[r] = bv;
    }
    if (r < Dq && tid < Nq) {
        g_A2[r * Nq + tid] = -expf(logA[r * Nq + tid]) * 1.44269504088896340736f;
    }
}

/* ---------------- layernorm: fp32 out + fp16 out ---------------- */
__global__ void ln_kernel(const float* __restrict__ x,
                          const float* __restrict__ w,
                          const float* __restrict__ b)
{
    int row = blockIdx.x;
    int tid = threadIdx.x;       /* 256 */
    const float4* x4 = reinterpret_cast<const float4*>(x) + (size_t)row * 256;
    float4 v = x4[tid];
    float sum = v.x + v.y + v.z + v.w;
    float sq  = v.x*v.x + v.y*v.y + v.z*v.z + v.w*v.w;

    #pragma unroll
    for (int o = 16; o > 0; o >>= 1) {
        sum += __shfl_down_sync(0xffffffffu, sum, o);
        sq  += __shfl_down_sync(0xffffffffu, sq, o);
    }
    __shared__ float red0[8], red1[8];
    int warp = tid >> 5, lane = tid & 31;
    if (lane == 0) { red0[warp] = sum; red1[warp] = sq; }
    __syncthreads();
    if (tid < 32) {
        float s1 = (tid < 8) ? red0[tid] : 0.f;
        float s2 = (tid < 8) ? red1[tid] : 0.f;
        #pragma unroll
        for (int o = 4; o > 0; o >>= 1) {
            s1 += __shfl_down_sync(0xffffffffu, s1, o);
            s2 += __shfl_down_sync(0xffffffffu, s2, o);
        }
        if (tid == 0) { red0[0] = s1; red1[0] = s2; }
    }
    __syncthreads();
    float mean = red0[0] * (1.0f / Dq);
    float var  = red1[0] * (1.0f / Dq) - mean * mean;
    float rs   = rsqrtf(var + 1e-5f);

    float4 wv = reinterpret_cast<const float4*>(w)[tid];
    float4 bv = reinterpret_cast<const float4*>(b)[tid];
    float4 o;
    o.x = (v.x - mean) * rs * wv.x + bv.x;
    o.y = (v.y - mean) * rs * wv.y + bv.y;
    o.z = (v.z - mean) * rs * wv.z + bv.z;
    o.w = (v.w - mean) * rs * wv.w + bv.w;
    reinterpret_cast<float4*>(g_h)[(size_t)row * 256 + tid] = o;

    __half q[4];
    q[0] = __float2half_rn(o.x); q[1] = __float2half_rn(o.y);
    q[2] = __float2half_rn(o.z); q[3] = __float2half_rn(o.w);
    *reinterpret_cast<uint2*>(g_hh + (size_t)row * Kq + tid * 4) = *reinterpret_cast<uint2*>(q);
}

/* ====== HMMA GEMM: fp16 1-term, BK=32, 3-stage, 2 CTAs/SM ====== */
#define BK5 32
#define KPADB 80
#define PLANEB (128 * KPADB)
#define STAGEB (2 * PLANEB)
#define NSTG 3
#define GSMEM (NSTG * STAGEB)     /* 61440 B */
#define NCHK5 (Kq / BK5)          /* 32 */

__device__ __forceinline__ void cp16(uint32_t dst, const void* src) {
    asm volatile("cp.async.cg.shared.global [%0], [%1], 16;" :: "r"(dst), "l"(src) : "memory");
}
__device__ __forceinline__ void cp_commit() {
    asm volatile("cp.async.commit_group;" ::: "memory");
}
template<int N> __device__ __forceinline__ void cp_wait() {
    asm volatile("cp.async.wait_group %0;" :: "n"(N) : "memory");
}
__device__ __forceinline__ void ldm_x4(uint32_t addr, uint32_t* r) {
    asm volatile("ldmatrix.sync.aligned.m8n8.x4.shared.b16 {%0,%1,%2,%3}, [%4];"
                 : "=r"(r[0]), "=r"(r[1]), "=r"(r[2]), "=r"(r[3]) : "r"(addr));
}
__device__ __forceinline__ void mma_f16(float* c, const uint32_t* a, const uint32_t* b) {
    asm volatile("mma.sync.aligned.m16n8k16.row.col.f32.f16.f16.f32 "
                 "{%0,%1,%2,%3}, {%4,%5,%6,%7}, {%8,%9}, {%0,%1,%2,%3};"
                 : "+f"(c[0]), "+f"(c[1]), "+f"(c[2]), "+f"(c[3])
                 : "r"(a[0]), "r"(a[1]), "r"(a[2]), "r"(a[3]), "r"(b[0]), "r"(b[1]));
}
__device__ __forceinline__ float softplus_f(float v) {
    return fmaxf(v, 0.f) + log1pf(expf(-fabsf(v)));
}

__device__ __forceinline__ void fill_stage(uint32_t sbase, int kc, int tid,
                                           const __half* A, const __half* B)
{
    const __half* srcs[2] = {A, B};
    #pragma unroll
    for (int p = 0; p < 2; p++) {
        #pragma unroll
        for (int i = 0; i < 2; i++) {
            int id = tid + i * 256;
            int row = id >> 2, q = id & 3;
            cp16(sbase + p * PLANEB + row * KPADB + q * 16,
                 srcs[p] + (size_t)row * Kq + kc * BK5 + q * 8);
        }
    }
}

__global__ __launch_bounds__(256, 2)
void gemm_hmma_kernel(const float* __restrict__ xres)
{
    extern __shared__ __align__(16) char dynsm[];
    uint32_t smb = smem_u32(dynsm);

    int tid  = threadIdx.x;
    int wid  = tid >> 5, lane = tid & 31;
    int n0   = blockIdx.x * 128;
    int m0   = blockIdx.y * 128;
    int wm   = wid >> 1;
    int wn   = wid & 1;

    const __half* Ah = g_hh + (size_t)m0 * Kq;
    const __half* Bh = g_Wh + (size_t)n0 * Kq;

    float acc[2][8][4];
    #pragma unroll
    for (int i = 0; i < 2; i++)
        #pragma unroll
        for (int j = 0; j < 8; j++)
            #pragma unroll
            for (int k = 0; k < 4; k++) acc[i][j][k] = 0.f;

    uint32_t a_off[2], b_off[8];
    #pragma unroll
    for (int mt = 0; mt < 2; mt++)
        a_off[mt] = (uint32_t)((wm * 32 + (lane & 15) + mt * 16) * KPADB + (lane >> 4) * 16);
    #pragma unroll
    for (int p = 0; p < 4; p++)
        b_off[p] = (uint32_t)((wn * 64 + (lane & 7) + ((lane >> 4) * 8) + p * 16) * KPADB
                              + ((lane >> 3) & 1) * 16);

    fill_stage(smb + 0 * STAGEB, 0, tid, Ah, Bh); cp_commit();
    fill_stage(smb + 1 * STAGEB, 1, tid, Ah, Bh); cp_commit();

    for (int kc = 0; kc < NCHK5; kc++) {
        int buf = kc % NSTG;
        if (kc == NCHK5 - 1) cp_wait<0>(); else cp_wait<1>();
        __syncthreads();
        if (kc + 2 < NCHK5) {
            fill_stage(smb + ((kc + 2) % NSTG) * STAGEB, kc + 2, tid, Ah, Bh);
            cp_commit();
        }

        uint32_t base = smb + buf * STAGEB;
        #pragma unroll
        for (int kk = 0; kk < 2; kk++) {
            uint32_t ko = (uint32_t)(kk * 32);
            uint32_t a[2][4], bt[8][2];
            #pragma unroll
            for (int mt = 0; mt < 2; mt++)
                ldm_x4(base + 0 * PLANEB + a_off[mt] + ko, a[mt]);
            #pragma unroll
            for (int p = 0; p < 4; p++) {
                uint32_t r4[4];
                ldm_x4(base + 1 * PLANEB + b_off[p] + ko, r4);
                bt[2*p][0] = r4[0]; bt[2*p][1] = r4[1];
                bt[2*p+1][0] = r4[2]; bt[2*p+1][1] = r4[3];
            }
            #pragma unroll
            for (int mt = 0; mt < 2; mt++)
                #pragma unroll
                for (int nt = 0; nt < 8; nt++)
                    mma_f16(acc[mt][nt], a[mt], bt[nt]);
        }
    }

    /* epilogue: bias + routing (packed pairs; x fused into lin) */
    int qrow = lane >> 2;
    int qcol = (lane & 3) * 2;
    #pragma unroll
    for (int mt = 0; mt < 2; mt++) {
        #pragma unroll
        for (int half = 0; half < 2; half++) {
            int m = m0 + wm * 32 + mt * 16 + qrow + half * 8;
            #pragma unroll
            for (int nt = 0; nt < 8; nt++) {
                int col = n0 + wn * 64 + nt * 8 + qcol;
                if (col >= NCAT) continue;
                float v0 = acc[mt][nt][half * 2 + 0] + g_bcat[col];
                float v1 = acc[mt][nt][half * 2 + 1] + g_bcat[col + 1];
                if (col < 1024) {
                    float2 hv = *reinterpret_cast<const float2*>(g_h + (size_t)m * Dq + col);
                    float sp0 = softplus_f(v0), sp1 = softplus_f(v1);
                    float4 o4 = make_float4(sp0, sp0 * hv.x, sp1, sp1 * hv.y);
                    *reinterpret_cast<float4*>(g_dtdh + ((size_t)m * Dq + col) * 2) = o4;
                } else if (col < 2048) {
                    int cc = col - 1024;
                    float2 xr = *reinterpret_cast<const float2*>(xres + (size_t)m * Dq + cc);
                    *reinterpret_cast<float2*>(g_lin + (size_t)m * Dq + cc) =
                        make_float2(v0 + xr.x, v1 + xr.y);
                } else if (col < 2064) {
                    int cc = col - 2048;
                    g_bc[((size_t)m * Nq + cc) * 2]     = v0;
                    g_bc[((size_t)m * Nq + cc + 1) * 2] = v1;
                } else {
                    int cc = col - 2064;
                    g_bc[((size_t)m * Nq + cc) * 2 + 1]     = v0;
                    g_bc[((size_t)m * Nq + cc + 1) * 2 + 1] = v1;
                }
            }
        }
    }
}

/* ====== scan v9: n-paired (2 states/thread), 8-lane reduce ====== */
/* block 256 = 32 d x 8 q (q owns n=2q,2q+1); grid (32, 4)          */
#define TP 16
#define DTDH_OFF 0        /* [16t][64]  = 1024 floats */
#define LL_OFF   1024     /* [16t][36]  =  576 floats (padded rows) */
#define BC_OFF   1600     /* [16t][32]  =  512 floats */
#define BUFSZ    2112
#define STG_OFF  (2 * BUFSZ)      /* stage: [16t][34] = 544 floats */

__device__ __forceinline__ void cp16_ca(uint32_t dst, const void* src) {
    asm volatile("cp.async.ca.shared.global [%0], [%1], 16;" :: "r"(dst), "l"(src) : "memory");
}
__device__ __forceinline__ float ex2f(float x) {
    float r;
    asm("ex2.approx.f32 %0, %1;" : "=f"(r) : "f"(x));
    return r;
}

__device__ __forceinline__ void scan_load_tile(uint32_t sbase, int buf, int t0,
                                               int b, int d0, int tid)
{
    /* 512 cp.async(16B) tasks over 256 threads: dtdh 256, ll 128, bc 128 */
    #pragma unroll
    for (int u = 0; u < 2; u++) {
        int task = tid + u * 256;
        const float* src;
        uint32_t doff;
        if (task < 256) {
            int t = task >> 4, j = task & 15;
            src  = g_dtdh + ((size_t)(b * Sq + t0 + t) * Dq + d0) * 2 + j * 4;
            doff = (uint32_t)(DTDH_OFF + t * 64 + j * 4);
        } else if (task < 384) {
            int idx = task - 256;
            int t = idx >> 3, j = idx & 7;
            src  = g_lin + (size_t)(b * Sq + t0 + t) * Dq + d0 + j * 4;
            doff = (uint32_t)(LL_OFF + t * 36 + j * 4);
        } else {
            int idx = task - 384;
            int t = idx >> 3, j = idx & 7;
            src  = g_bc + (size_t)(b * Sq + t0 + t) * (Nq * 2) + j * 4;
            doff = (uint32_t)(BC_OFF + t * 32 + j * 4);
        }
        cp16_ca(sbase + (uint32_t)(buf * BUFSZ) * 4u + doff * 4u, src);
    }
}

__global__ __launch_bounds__(256)
void scan_kernel(float* __restrict__ out)
{
    __shared__ __align__(16) float smem[2 * BUFSZ + 16 * 34];   /* ~19 KB */
    uint32_t sbase = smem_u32(smem);
    float* stage = smem + STG_OFF;

    int b   = blockIdx.y;
    int tid = threadIdx.x;          /* 256 = 32 d x 8 q */
    int q   = tid & 7;
    int dl  = tid >> 3;             /* 0..31 */
    int d0  = blockIdx.x * 32;
    int d   = d0 + dl;

    /* output-store mapping: thread -> (t = tid>>4, d-pair j = tid&15) */
    int ot = tid >> 4;              /* 0..15 */
    int oj = tid & 15;              /* 0..15 */

    float2 a2 = *reinterpret_cast<const float2*>(g_A2 + d * Nq + q * 2);
    float s0 = 0.f, s1 = 0.f;

    scan_load_tile(sbase, 0, 0, b, d0, tid);
    cp_commit();

    const int NT = Sq / TP;          /* 256 */
    for (int j = 0; j < NT; j++) {
        int buf = j & 1;
        int t0  = j * TP;

        __syncthreads();
        if (j + 1 < NT) {
            scan_load_tile(sbase, buf ^ 1, t0 + TP, b, d0, tid);
            cp_commit();
            cp_wait<1>();
        } else {
            cp_wait<0>();
        }
        __syncthreads();

        const float* sb = smem + buf * BUFSZ;

        /* phase 1: recurrence, 2 states per thread */
        float pv[TP];
        #pragma unroll
        for (int k = 0; k < TP; k++) {
            float2 dd   = *reinterpret_cast<const float2*>(sb + DTDH_OFF + k * 64 + dl * 2);
            float4 bcq  = *reinterpret_cast<const float4*>(sb + BC_OFF + k * 32 + q * 4);
            float dA0 = ex2f(dd.x * a2.x);
            float dA1 = ex2f(dd.x * a2.y);
            s0 = fmaf(dA0, s0, dd.y * bcq.x);
            s1 = fmaf(dA1, s1, dd.y * bcq.z);
            pv[k] = fmaf(s1, bcq.w, s0 * bcq.y);
        }

        /* phase 2: 8x8 transpose of float2 blocks over q-lanes.
           After: lane q's block m = original lane m's block q
                  = partial sums for t=2q,2q+1 from lane m. */
        #pragma unroll
        for (int o = 1; o <= 4; o <<= 1) {
            bool up = (q & o) != 0;
            #pragma unroll
            for (int m = 0; m < 8; m++) {
                if (m & o) continue;
                int mB = m + o;
                float g0 = up ? pv[2*m]   : pv[2*mB];
                float g1 = up ? pv[2*m+1] : pv[2*mB+1];
                float r0 = __shfl_xor_sync(0xffffffffu, g0, o);
                float r1 = __shfl_xor_sync(0xffffffffu, g1, o);
                if (up) { pv[2*m] = r0;  pv[2*m+1] = r1; }
                else    { pv[2*mB] = r0; pv[2*mB+1] = r1; }
            }
        }
        /* sum the 8 blocks: thread (dl,q) now owns outputs t=2q,2q+1 at d=dl */
        float y0 = pv[0], y1 = pv[1];
        #pragma unroll
        for (int m = 1; m < 8; m++) { y0 += pv[2*m]; y1 += pv[2*m+1]; }

        stage[(2*q)   * 34 + dl] = y0;
        stage[(2*q+1) * 34 + dl] = y1;
        __syncthreads();

        /* coalesced float2 store: warp = 2 t x 16 d-pairs */
        float2 sv = *reinterpret_cast<const float2*>(stage + ot * 34 + oj * 2);
        float2 lv = *reinterpret_cast<const float2*>(sb + LL_OFF + ot * 36 + oj * 2);
        *reinterpret_cast<float2*>(out + (size_t)(b * Sq + t0 + ot) * Dq + d0 + oj * 2) =
            make_float2(lv.x + sv.x, lv.y + sv.y);
    }
}

/* ------------------------------- launch ------------------------------- */
extern "C" void kernel_launch(void* const* d_in, const int* in_sizes, int n_in,
                              void* d_out, int out_size)
{
    const float* x    = (const float*)d_in[0];
    const float* logA = (const float*)d_in[1];
    const float* Wd   = (const float*)d_in[2];
    const float* bd   = (const float*)d_in[3];
    const float* Wb   = (const float*)d_in[4];
    const float* bb   = (const float*)d_in[5];
    const float* Wc   = (const float*)d_in[6];
    const float* bc   = (const float*)d_in[7];
    const float* WDp  = (const float*)d_in[8];
    const float* bD   = (const float*)d_in[9];
    const float* lnw  = (const float*)d_in[10];
    const float* lnb  = (const float*)d_in[11];
    float* out = (float*)d_out;

    cudaFuncSetAttribute(gemm_hmma_kernel,
                         cudaFuncAttributeMaxDynamicSharedMemorySize, GSMEM);

    prep_kernel<<<NPAD, 256>>>(logA, Wd, bd, Wb, bb, Wc, bc, WDp, bD);
    ln_kernel<<<Mq, 256>>>(x, lnw, lnb);
    dim3 ggrid(NPAD / 128, Mq / 128);            /* 17 x 128 */
    gemm_hmma_kernel<<<ggrid, 256, GSMEM>>>(x);
    dim3 sgrid(Dq / 32, Bq);                     /* 32 x 4 */
    scan_kernel<<<sgrid, 256>>>(out);
}